// round 12
// baseline (speedup 1.0000x reference)
#include <cuda_runtime.h>
#include <cuda_fp16.h>
#include <math.h>

// ---------------------------------------------------------------------------
// Problem constants
// ---------------------------------------------------------------------------
#define SEQ      4096
#define DIM      2048
#define NH       16
#define NKV      4
#define HD       128
#define KVDIM    (NKV*HD)          // 512
#define QKVN     (DIM + 2*KVDIM)   // 3072
#define NROWS_W  (QKVN + DIM)      // 5120 quantize rows

// ---------------------------------------------------------------------------
// Device-global scratch (no cudaMalloc allowed)
// ---------------------------------------------------------------------------
__device__ __half  g_Wqkv[QKVN * DIM];   // TERNARY {-1,0,1} fp16 [3072][2048]
__device__ __half  g_Wp  [DIM  * DIM];   // TERNARY fp16 [2048][2048]
__device__ float   g_sqkv[QKVN];         // per-row scales
__device__ float   g_sp  [DIM];
__device__ __half  g_x_h [SEQ * DIM];    // x in fp16
__device__ float   g_QKV [SEQ * QKVN];   // qkv output f32 (for rmsnorm precision)
__device__ __half  g_QKVh[SEQ * QKVN];   // qkv fp16 (q/k overwritten post-rope)
__device__ __half  g_Yh  [SEQ * DIM];    // attention output fp16
__device__ float   g_cos [SEQ * (HD/2)];
__device__ float   g_sin [SEQ * (HD/2)];
__device__ double  g_invf[HD/2];

// ---------------------------------------------------------------------------
// helpers
// ---------------------------------------------------------------------------
__device__ __forceinline__ void mma_f16(float d[4], const unsigned a[4], const unsigned b[2]) {
    asm volatile(
        "mma.sync.aligned.m16n8k16.row.col.f32.f16.f16.f32 "
        "{%0,%1,%2,%3},{%4,%5,%6,%7},{%8,%9},{%0,%1,%2,%3};"
        : "+f"(d[0]), "+f"(d[1]), "+f"(d[2]), "+f"(d[3])
        : "r"(a[0]), "r"(a[1]), "r"(a[2]), "r"(a[3]), "r"(b[0]), "r"(b[1]));
}

__device__ __forceinline__ void ldsm_x4(unsigned r[4], const __half* p) {
    unsigned addr = (unsigned)__cvta_generic_to_shared(p);
    asm volatile("ldmatrix.sync.aligned.m8n8.x4.shared.b16 {%0,%1,%2,%3}, [%4];"
                 : "=r"(r[0]), "=r"(r[1]), "=r"(r[2]), "=r"(r[3]) : "r"(addr));
}
__device__ __forceinline__ void ldsm_x4t(unsigned r[4], const __half* p) {
    unsigned addr = (unsigned)__cvta_generic_to_shared(p);
    asm volatile("ldmatrix.sync.aligned.m8n8.x4.trans.shared.b16 {%0,%1,%2,%3}, [%4];"
                 : "=r"(r[0]), "=r"(r[1]), "=r"(r[2]), "=r"(r[3]) : "r"(addr));
}

__device__ __forceinline__ void cp_async16(__half* smem_dst, const __half* gmem_src) {
    unsigned s = (unsigned)__cvta_generic_to_shared(smem_dst);
    asm volatile("cp.async.cg.shared.global [%0], [%1], 16;" :: "r"(s), "l"(gmem_src));
}
#define CP_COMMIT()  asm volatile("cp.async.commit_group;")
#define CP_WAIT(N)   asm volatile("cp.async.wait_group %0;" :: "n"(N))

// ---------------------------------------------------------------------------
// 1) RoPE tables: fp64 invf + fp64 range reduction + fast fp32 sincos.
// ---------------------------------------------------------------------------
__global__ void invf_kernel() {
    int j = threadIdx.x;
    if (j < HD/2) g_invf[j] = pow(10000.0, -(double)j / 64.0);
}

__global__ void rope_table_kernel() {
    int idx = blockIdx.x * blockDim.x + threadIdx.x;
    if (idx >= SEQ * (HD/2)) return;
    int t = idx >> 6;
    int j = idx & 63;
    double ang = (double)t * g_invf[j];
    double q   = rint(ang * 0.15915494309189535);
    float  r   = (float)(ang - q * 6.283185307179586476);
    float sn, cn;
    __sincosf(r, &sn, &cn);
    g_cos[idx] = cn;
    g_sin[idx] = sn;
}

// ---------------------------------------------------------------------------
// 2) x -> fp16
// ---------------------------------------------------------------------------
__global__ __launch_bounds__(256) void xh_kernel(const float* __restrict__ x) {
    int i = (blockIdx.x * 256 + threadIdx.x) * 4;
    float4 v = *(const float4*)(x + i);
    *(__half2*)(g_x_h + i)     = __floats2half2_rn(v.x, v.y);
    *(__half2*)(g_x_h + i + 2) = __floats2half2_rn(v.z, v.w);
}

// ---------------------------------------------------------------------------
// 3) BitLinear quantize -> TERNARY fp16 + per-row scale. Vectorized:
//    each thread owns 8 consecutive elems (2 float4 in, 1 16B half-store out).
// ---------------------------------------------------------------------------
__global__ __launch_bounds__(256) void quantize_kernel(
    const float* __restrict__ wq, const float* __restrict__ wk,
    const float* __restrict__ wv, const float* __restrict__ wp)
{
    int row = blockIdx.x;
    const float* src; __half* dst; float* sdst;
    if      (row < DIM)        { src = wq + (size_t)row * DIM;                 dst = g_Wqkv + (size_t)row * DIM; sdst = g_sqkv + row; }
    else if (row < DIM + KVDIM){ src = wk + (size_t)(row - DIM) * DIM;         dst = g_Wqkv + (size_t)row * DIM; sdst = g_sqkv + row; }
    else if (row < QKVN)       { src = wv + (size_t)(row - DIM - KVDIM) * DIM; dst = g_Wqkv + (size_t)row * DIM; sdst = g_sqkv + row; }
    else                       { src = wp + (size_t)(row - QKVN) * DIM;        dst = g_Wp + (size_t)(row - QKVN) * DIM; sdst = g_sp + (row - QKVN); }

    int tid = threadIdx.x;
    float4 v0 = *(const float4*)(src + tid * 8);
    float4 v1 = *(const float4*)(src + tid * 8 + 4);
    float a = fabsf(v0.x) + fabsf(v0.y) + fabsf(v0.z) + fabsf(v0.w)
            + fabsf(v1.x) + fabsf(v1.y) + fabsf(v1.z) + fabsf(v1.w);
    #pragma unroll
    for (int o = 16; o > 0; o >>= 1) a += __shfl_xor_sync(0xffffffffu, a, o);
    __shared__ float wsum[8];
    if ((tid & 31) == 0) wsum[tid >> 5] = a;
    __syncthreads();
    float tot = wsum[0] + wsum[1] + wsum[2] + wsum[3]
              + wsum[4] + wsum[5] + wsum[6] + wsum[7];
    float s = fmaxf(tot * (1.f / (float)DIM), 1e-5f);
    if (tid == 0) *sdst = s;

    float inv = 1.f / s;
    float w[8] = { v0.x, v0.y, v0.z, v0.w, v1.x, v1.y, v1.z, v1.w };
    __half h[8];
    #pragma unroll
    for (int i = 0; i < 8; i++) {
        float q = rintf(w[i] * inv);
        h[i] = __float2half_rn(fminf(fmaxf(q, -1.f), 1.f));   // -1/0/1 exact
    }
    *(uint4*)(dst + tid * 8) = *(uint4*)h;
}

// ---------------------------------------------------------------------------
// 4) FP16 GEMM, cp.async double-buffered, LDSM fragments.
//    BM=BN=128, BK=64, 256 threads = 8 warps (4x2), warp tile 32x64.
// ---------------------------------------------------------------------------
#define GSTR 88
#define GSTG (128 * GSTR)    // halves per stage per operand

__device__ __forceinline__ void gemm_core(
    const __half* __restrict__ A, const __half* __restrict__ B,
    const float* __restrict__ sc, float* __restrict__ C,
    __half* __restrict__ Ch, int N)
{
    extern __shared__ __half smh[];
    __half* As = smh;               // [2][128*88]
    __half* Bs = smh + 2 * GSTG;    // [2][128*88]
    const int K = DIM;
    int tid = threadIdx.x, warp = tid >> 5, lane = tid & 31;
    int g = lane >> 2, t = lane & 3;
    int wm = (warp & 3) * 32, wn = (warp >> 2) * 64;
    int l15 = lane & 15, lh = lane >> 4, l7 = lane & 7, lk = (lane >> 3) & 1;
    const __half* Ab = A + (size_t)blockIdx.y * 128 * K;
    const __half* Bb = B + (size_t)blockIdx.x * 128 * K;

    float acc[2][8][4];
    #pragma unroll
    for (int mt = 0; mt < 2; mt++)
        #pragma unroll
        for (int nt = 0; nt < 8; nt++)
            #pragma unroll
            for (int r = 0; r < 4; r++) acc[mt][nt][r] = 0.f;

    auto load_stage = [&](int stage, int k0) {
        __half* Ad = As + stage * GSTG;
        __half* Bd = Bs + stage * GSTG;
        #pragma unroll
        for (int i = 0; i < 4; i++) {
            int l = tid + i * 256;
            int row = l >> 3, c8 = (l & 7) * 8;
            cp_async16(Ad + row * GSTR + c8, Ab + (size_t)row * K + k0 + c8);
            cp_async16(Bd + row * GSTR + c8, Bb + (size_t)row * K + k0 + c8);
        }
        CP_COMMIT();
    };

    load_stage(0, 0);
    const int nIter = K / 64;   // 32
    for (int it = 0; it < nIter; it++) {
        CP_WAIT(0);
        __syncthreads();
        if (it + 1 < nIter) load_stage((it + 1) & 1, (it + 1) * 64);

        const __half* Ac = As + (it & 1) * GSTG;
        const __half* Bc = Bs + (it & 1) * GSTG;
        #pragma unroll
        for (int kk = 0; kk < 64; kk += 16) {
            unsigned a[2][4];
            #pragma unroll
            for (int mt = 0; mt < 2; mt++)
                ldsm_x4(a[mt], Ac + (wm + mt * 16 + l15) * GSTR + kk + lh * 8);
            #pragma unroll
            for (int n2 = 0; n2 < 4; n2++) {
                unsigned b[4];
                ldsm_x4(b, Bc + (wn + n2 * 16 + lh * 8 + l7) * GSTR + kk + lk * 8);
                mma_f16(acc[0][2*n2],     a[0], b);
                mma_f16(acc[1][2*n2],     a[1], b);
                mma_f16(acc[0][2*n2 + 1], a[0], b + 2);
                mma_f16(acc[1][2*n2 + 1], a[1], b + 2);
            }
        }
        __syncthreads();
    }

    int brow = blockIdx.y * 128, bcol = blockIdx.x * 128;
    #pragma unroll
    for (int mt = 0; mt < 2; mt++) {
        int r0 = brow + wm + mt * 16 + g;
        #pragma unroll
        for (int nt = 0; nt < 8; nt++) {
            int c = bcol + wn + nt * 8 + 2 * t;
            float s0 = sc[c], s1 = sc[c + 1];
            float v00 = acc[mt][nt][0] * s0, v01 = acc[mt][nt][1] * s1;
            float v10 = acc[mt][nt][2] * s0, v11 = acc[mt][nt][3] * s1;
            *(float2*)(C + (size_t)r0 * N + c)       = make_float2(v00, v01);
            *(float2*)(C + (size_t)(r0 + 8) * N + c) = make_float2(v10, v11);
            if (Ch) {
                *(__half2*)(Ch + (size_t)r0 * N + c)       = __floats2half2_rn(v00, v01);
                *(__half2*)(Ch + (size_t)(r0 + 8) * N + c) = __floats2half2_rn(v10, v11);
            }
        }
    }
}

__global__ __launch_bounds__(256, 2) void gemm_qkv_kernel() {
    gemm_core(g_x_h, g_Wqkv, g_sqkv, g_QKV, g_QKVh, QKVN);
}
__global__ __launch_bounds__(256, 2) void gemm_proj_kernel(float* __restrict__ out) {
    gemm_core(g_Yh, g_Wp, g_sp, out, (__half*)0, DIM);
}
static const int GEMM_SMEM = 4 * GSTG * (int)sizeof(__half);  // 90112

// ---------------------------------------------------------------------------
// 5) Q/K post: RMSNorm (eps=2^-23) -> RoPE -> gain; f32 in, fp16 out.
// ---------------------------------------------------------------------------
__global__ __launch_bounds__(256) void qk_post_kernel(const float* __restrict__ gain) {
    int widx = blockIdx.x * 8 + (threadIdx.x >> 5);
    int lane = threadIdx.x & 31;
    if (widx >= SEQ * (NH + NKV)) return;
    int pos  = widx / (NH + NKV);
    int slot = widx - pos * (NH + NKV);

    size_t off; float gv = 1.f;
    if (slot < NH) { off = (size_t)pos * QKVN + slot * HD; gv = gain[slot]; }
    else           { off = (size_t)pos * QKVN + DIM + (slot - NH) * HD; }
    const float* p = g_QKV + off;
    __half* ph = g_QKVh + off;

    float v0 = p[lane], v1 = p[lane+32], v2 = p[lane+64], v3 = p[lane+96];
    float ss = v0*v0 + v1*v1 + v2*v2 + v3*v3;
    #pragma unroll
    for (int o = 16; o > 0; o >>= 1) ss += __shfl_xor_sync(0xffffffffu, ss, o);
    float ms = ss * (1.f / 128.f) + 1.1920928955078125e-07f;
    float r  = rsqrtf(ms);
    r = r * (1.5f - 0.5f * ms * r * r);
    v0 *= r; v1 *= r; v2 *= r; v3 *= r;

    const float* cr = g_cos + pos * 64;
    const float* sr = g_sin + pos * 64;
    float c0 = cr[lane], s0 = sr[lane], c1 = cr[lane+32], s1 = sr[lane+32];
    float o0 =  v0 * c0 + v2 * s0;
    float o2 = -v0 * s0 + v2 * c0;
    float o1 =  v1 * c1 + v3 * s1;
    float o3 = -v1 * s1 + v3 * c1;
    ph[lane]    = __float2half_rn(o0 * gv);
    ph[lane+32] = __float2half_rn(o1 * gv);
    ph[lane+64] = __float2half_rn(o2 * gv);
    ph[lane+96] = __float2half_rn(o3 * gv);
}

// ---------------------------------------------------------------------------
// 6) FP16 flash attention, cp.async pipelined, LDSM fragments, 2 blocks/SM.
// ---------------------------------------------------------------------------
#define FSTR 136
#define PSTR 72

__global__ __launch_bounds__(256, 2) void flash_kernel() {
    extern __shared__ __half smf[];
    __half* Qs  = smf;                    // [128][136]
    __half* Ks0 = Qs  + 128 * FSTR;       // [64][136]
    __half* Ks1 = Ks0 + 64 * FSTR;        // [64][136]
    __half* Vs  = Ks1 + 64 * FSTR;        // [64][136]
    __half* Ps  = Vs  + 64 * FSTR;        // [128][72]

    int qtile = gridDim.x - 1 - blockIdx.x;   // longest first
    int h = blockIdx.y, kvh = h >> 2;
    int qbase = qtile * 128;
    int tid = threadIdx.x, warp = tid >> 5, lane = tid & 31;
    int g = lane >> 2, t = lane & 3;
    int l15 = lane & 15, lh = lane >> 4, l7 = lane & 7, lk = (lane >> 3) & 1;
    int wbase = warp * 16;
    const float scale = 0.08838834764831845f;
    const float L2E = 1.4426950408889634f;

    const __half* qp = g_QKVh + (size_t)qbase * QKVN + h * HD;
    #pragma unroll
    for (int i = 0; i < 8; i++) {
        int l = tid + i * 256;
        int row = l >> 4, c8 = (l & 15) * 8;
        cp_async16(Qs + row * FSTR + c8, qp + (size_t)row * QKVN + c8);
    }
    CP_COMMIT();

    auto issueK = [&](int j, __half* Kbuf) {
        const __half* kp = g_QKVh + (size_t)(j * 64) * QKVN + DIM + kvh * HD;
        #pragma unroll
        for (int i = 0; i < 4; i++) {
            int l = tid + i * 256;
            int row = l >> 4, c8 = (l & 15) * 8;
            cp_async16(Kbuf + row * FSTR + c8, kp + (size_t)row * QKVN + c8);
        }
        CP_COMMIT();
    };
    auto issueV = [&](int j) {
        const __half* vp = g_QKVh + (size_t)(j * 64) * QKVN + DIM + KVDIM + kvh * HD;
        #pragma unroll
        for (int i = 0; i < 4; i++) {
            int l = tid + i * 256;
            int row = l >> 4, c8 = (l & 15) * 8;
            cp_async16(Vs + row * FSTR + c8, vp + (size_t)row * QKVN + c8);
        }
        CP_COMMIT();
    };

    float oacc[16][4];
    #pragma unroll
    for (int nt = 0; nt < 16; nt++)
        #pragma unroll
        for (int r = 0; r < 4; r++) oacc[nt][r] = 0.f;
    float m0 = -1e30f, m1 = -1e30f, l0 = 0.f, l1 = 0.f;

    int row0 = qbase + wbase + g, row1 = row0 + 8;
    int jmax = 2 * qtile + 1;

    issueK(0, Ks0);   // groups in flight: [Q, K0]

    for (int j = 0; j <= jmax; j++) {
        int kvbase = j * 64;
        __syncthreads();               // Vs free (prev PV done)
        issueV(j);
        int jn = (j + 1 <= jmax) ? j + 1 : jmax;
        issueK(jn, (j & 1) ? Ks0 : Ks1);
        CP_WAIT(2);                    // Q + K(j) ready
        __syncthreads();
        const __half* Kc = (j & 1) ? Ks1 : Ks0;

        // --- S = Q @ K^T ---
        float sacc[8][4];
        #pragma unroll
        for (int nt = 0; nt < 8; nt++)
            #pragma unroll
            for (int r = 0; r < 4; r++) sacc[nt][r] = 0.f;
        #pragma unroll
        for (int kk = 0; kk < 128; kk += 16) {
            unsigned a[4];
            ldsm_x4(a, Qs + (wbase + l15) * FSTR + kk + lh * 8);
            #pragma unroll
            for (int n2 = 0; n2 < 4; n2++) {
                unsigned b[4];
                ldsm_x4(b, Kc + (n2 * 16 + lh * 8 + l7) * FSTR + kk + lk * 8);
                mma_f16(sacc[2*n2],     a, b);
                mma_f16(sacc[2*n2 + 1], a, b + 2);
            }
        }

        // --- scale + causal mask + online softmax ---
        float mn0 = m0, mn1 = m1;
        #pragma unroll
        for (int nt = 0; nt < 8; nt++) {
            int c0 = kvbase + nt * 8 + 2 * t, c1 = c0 + 1;
            float v0 = (c0 <= row0) ? sacc[nt][0] * scale : -1e30f;
            float v1 = (c1 <= row0) ? sacc[nt][1] * scale : -1e30f;
            float v2 = (c0 <= row1) ? sacc[nt][2] * scale : -1e30f;
            float v3 = (c1 <= row1) ? sacc[nt][3] * scale : -1e30f;
            sacc[nt][0] = v0; sacc[nt][1] = v1; sacc[nt][2] = v2; sacc[nt][3] = v3;
            mn0 = fmaxf(mn0, fmaxf(v0, v1));
            mn1 = fmaxf(mn1, fmaxf(v2, v3));
        }
        mn0 = fmaxf(mn0, __shfl_xor_sync(0xffffffffu, mn0, 1));
        mn0 = fmaxf(mn0, __shfl_xor_sync(0xffffffffu, mn0, 2));
        mn1 = fmaxf(mn1, __shfl_xor_sync(0xffffffffu, mn1, 1));
        mn1 = fmaxf(mn1, __shfl_xor_sync(0xffffffffu, mn1, 2));
        float a0 = exp2f((m0 - mn0) * L2E);
        float a1 = exp2f((m1 - mn1) * L2E);
        m0 = mn0; m1 = mn1;
        float s0 = 0.f, s1 = 0.f;
        __half* pr0 = Ps + (wbase + g) * PSTR + 2 * t;
        __half* pr1 = pr0 + 8 * PSTR;
        #pragma unroll
        for (int nt = 0; nt < 8; nt++) {
            float p0 = exp2f((sacc[nt][0] - m0) * L2E);
            float p1 = exp2f((sacc[nt][1] - m0) * L2E);
            float p2 = exp2f((sacc[nt][2] - m1) * L2E);
            float p3 = exp2f((sacc[nt][3] - m1) * L2E);
            s0 += p0 + p1; s1 += p2 + p3;
            *(__half2*)(pr0 + nt * 8) = __floats2half2_rn(p0, p1);
            *(__half2*)(pr1 + nt * 8) = __floats2half2_rn(p2, p3);
        }
        s0 += __shfl_xor_sync(0xffffffffu, s0, 1);
        s0 += __shfl_xor_sync(0xffffffffu, s0, 2);
        s1 += __shfl_xor_sync(0xffffffffu, s1, 1);
        s1 += __shfl_xor_sync(0xffffffffu, s1, 2);
        l0 = l0 * a0 + s0;
        l1 = l1 * a1 + s1;
        #pragma unroll
        for (int nt = 0; nt < 16; nt++) {
            oacc[nt][0] *= a0; oacc[nt][1] *= a0;
            oacc[nt][2] *= a1; oacc[nt][3] *= a1;
        }

        CP_WAIT(1);                    // V(j) ready (K(j+1) may pend)
        __syncthreads();

        // --- O += P @ V  (V b-frags via ldmatrix.trans) ---
        #pragma unroll
        for (int kk = 0; kk < 64; kk += 16) {
            unsigned a[4];
            ldsm_x4(a, Ps + (wbase + l15) * PSTR + kk + lh * 8);
            #pragma unroll
            for (int n2 = 0; n2 < 8; n2++) {
                unsigned b[4];
                ldsm_x4t(b, Vs + (kk + lk * 8 + l7) * FSTR + n2 * 16 + lh * 8);
                mma_f16(oacc[2*n2],     a, b);
                mma_f16(oacc[2*n2 + 1], a, b + 2);
            }
        }
    }

    // --- epilogue: O /= l, write Yh (fp16) ---
    float i0 = 1.f / l0, i1 = 1.f / l1;
    __half* y0 = g_Yh + (size_t)(qbase + wbase + g) * DIM + h * HD + 2 * t;
    __half* y1 = y0 + 8 * DIM;
    #pragma unroll
    for (int nt = 0; nt < 16; nt++) {
        *(__half2*)(y0 + nt * 8) = __floats2half2_rn(oacc[nt][0] * i0, oacc[nt][1] * i0);
        *(__half2*)(y1 + nt * 8) = __floats2half2_rn(oacc[nt][2] * i1, oacc[nt][3] * i1);
    }
}

static const int FLASH_SMEM =
    (128 * FSTR + 2 * 64 * FSTR + 64 * FSTR + 128 * PSTR) * (int)sizeof(__half);  // 105472

// ---------------------------------------------------------------------------
// Launch
// ---------------------------------------------------------------------------
extern "C" void kernel_launch(void* const* d_in, const int* in_sizes, int n_in,
                              void* d_out, int out_size)
{
    const float* x    = (const float*)d_in[0];
    const float* wq   = (const float*)d_in[1];
    const float* wk   = (const float*)d_in[2];
    const float* wv   = (const float*)d_in[3];
    const float* wp   = (const float*)d_in[4];
    const float* gain = (const float*)d_in[5];
    float* out = (float*)d_out;

    cudaFuncSetAttribute(flash_kernel,
                         cudaFuncAttributeMaxDynamicSharedMemorySize, FLASH_SMEM);
    cudaFuncSetAttribute(gemm_qkv_kernel,
                         cudaFuncAttributeMaxDynamicSharedMemorySize, GEMM_SMEM);
    cudaFuncSetAttribute(gemm_proj_kernel,
                         cudaFuncAttributeMaxDynamicSharedMemorySize, GEMM_SMEM);

    invf_kernel<<<1, 64>>>();
    rope_table_kernel<<<(SEQ * (HD/2) + 255) / 256, 256>>>();
    xh_kernel<<<SEQ * DIM / 1024, 256>>>(x);
    quantize_kernel<<<NROWS_W, 256>>>(wq, wk, wv, wp);
    gemm_qkv_kernel<<<dim3(QKVN / 128, SEQ / 128), 256, GEMM_SMEM>>>();
    qk_post_kernel<<<(SEQ * (NH + NKV) + 7) / 8, 256>>>(gain);
    flash_kernel<<<dim3(SEQ / 128, NH), 256, FLASH_SMEM>>>();
    gemm_proj_kernel<<<dim3(DIM / 128, SEQ / 128), 256, GEMM_SMEM>>>(out);
}

// round 13
// speedup vs baseline: 1.2533x; 1.2533x over previous
#include <cuda_runtime.h>
#include <cuda_fp16.h>
#include <math.h>

// ---------------------------------------------------------------------------
// Problem constants
// ---------------------------------------------------------------------------
#define SEQ      4096
#define DIM      2048
#define NH       16
#define NKV      4
#define HD       128
#define KVDIM    (NKV*HD)          // 512
#define QKVN     (DIM + 2*KVDIM)   // 3072
#define NROWS_W  (QKVN + DIM)      // 5120 quantize rows

// ---------------------------------------------------------------------------
// Device-global scratch (no cudaMalloc allowed)
// ---------------------------------------------------------------------------
__device__ __half  g_Wqkv[QKVN * DIM];   // TERNARY {-1,0,1} fp16 [3072][2048]
__device__ __half  g_Wp  [DIM  * DIM];   // TERNARY fp16 [2048][2048]
__device__ float   g_sqkv[QKVN];         // per-row scales
__device__ float   g_sp  [DIM];
__device__ __half  g_x_h [SEQ * DIM];    // x in fp16
__device__ float   g_QKV [SEQ * QKVN];   // qkv output f32 (for rmsnorm precision)
__device__ __half  g_QKVh[SEQ * QKVN];   // qkv fp16 (q/k overwritten post-rope)
__device__ __half  g_Yh  [SEQ * DIM];    // attention output fp16
__device__ float   g_cos [SEQ * (HD/2)];
__device__ float   g_sin [SEQ * (HD/2)];
__device__ double  g_invf[HD/2];

// ---------------------------------------------------------------------------
// helpers
// ---------------------------------------------------------------------------
__device__ __forceinline__ void mma_f16(float d[4], const unsigned a[4], const unsigned b[2]) {
    asm volatile(
        "mma.sync.aligned.m16n8k16.row.col.f32.f16.f16.f32 "
        "{%0,%1,%2,%3},{%4,%5,%6,%7},{%8,%9},{%0,%1,%2,%3};"
        : "+f"(d[0]), "+f"(d[1]), "+f"(d[2]), "+f"(d[3])
        : "r"(a[0]), "r"(a[1]), "r"(a[2]), "r"(a[3]), "r"(b[0]), "r"(b[1]));
}

__device__ __forceinline__ void cp_async16(__half* smem_dst, const __half* gmem_src) {
    unsigned s = (unsigned)__cvta_generic_to_shared(smem_dst);
    asm volatile("cp.async.cg.shared.global [%0], [%1], 16;" :: "r"(s), "l"(gmem_src));
}
#define CP_COMMIT()  asm volatile("cp.async.commit_group;")
#define CP_WAIT(N)   asm volatile("cp.async.wait_group %0;" :: "n"(N))

__device__ __forceinline__ unsigned pack2(__half lo, __half hi) {
    __half2 h = __halves2half2(lo, hi);
    return *(unsigned*)&h;
}

// ---------------------------------------------------------------------------
// 1) RoPE tables: fp64 invf + fp64 range reduction + fast fp32 sincos.
// ---------------------------------------------------------------------------
__global__ void invf_kernel() {
    int j = threadIdx.x;
    if (j < HD/2) g_invf[j] = pow(10000.0, -(double)j / 64.0);
}

__global__ void rope_table_kernel() {
    int idx = blockIdx.x * blockDim.x + threadIdx.x;
    if (idx >= SEQ * (HD/2)) return;
    int t = idx >> 6;
    int j = idx & 63;
    double ang = (double)t * g_invf[j];
    double q   = rint(ang * 0.15915494309189535);
    float  r   = (float)(ang - q * 6.283185307179586476);
    float sn, cn;
    __sincosf(r, &sn, &cn);
    g_cos[idx] = cn;
    g_sin[idx] = sn;
}

// ---------------------------------------------------------------------------
// 2) x -> fp16
// ---------------------------------------------------------------------------
__global__ __launch_bounds__(256) void xh_kernel(const float* __restrict__ x) {
    int i = (blockIdx.x * 256 + threadIdx.x) * 4;
    float4 v = *(const float4*)(x + i);
    *(__half2*)(g_x_h + i)     = __floats2half2_rn(v.x, v.y);
    *(__half2*)(g_x_h + i + 2) = __floats2half2_rn(v.z, v.w);
}

// ---------------------------------------------------------------------------
// 3) BitLinear quantize -> TERNARY fp16 + per-row scale. Vectorized:
//    each thread owns 8 consecutive elems (2 float4 in, 1 16B half-store out).
// ---------------------------------------------------------------------------
__global__ __launch_bounds__(256) void quantize_kernel(
    const float* __restrict__ wq, const float* __restrict__ wk,
    const float* __restrict__ wv, const float* __restrict__ wp)
{
    int row = blockIdx.x;
    const float* src; __half* dst; float* sdst;
    if      (row < DIM)        { src = wq + (size_t)row * DIM;                 dst = g_Wqkv + (size_t)row * DIM; sdst = g_sqkv + row; }
    else if (row < DIM + KVDIM){ src = wk + (size_t)(row - DIM) * DIM;         dst = g_Wqkv + (size_t)row * DIM; sdst = g_sqkv + row; }
    else if (row < QKVN)       { src = wv + (size_t)(row - DIM - KVDIM) * DIM; dst = g_Wqkv + (size_t)row * DIM; sdst = g_sqkv + row; }
    else                       { src = wp + (size_t)(row - QKVN) * DIM;        dst = g_Wp + (size_t)(row - QKVN) * DIM; sdst = g_sp + (row - QKVN); }

    int tid = threadIdx.x;
    float4 v0 = *(const float4*)(src + tid * 8);
    float4 v1 = *(const float4*)(src + tid * 8 + 4);
    float a = fabsf(v0.x) + fabsf(v0.y) + fabsf(v0.z) + fabsf(v0.w)
            + fabsf(v1.x) + fabsf(v1.y) + fabsf(v1.z) + fabsf(v1.w);
    #pragma unroll
    for (int o = 16; o > 0; o >>= 1) a += __shfl_xor_sync(0xffffffffu, a, o);
    __shared__ float wsum[8];
    if ((tid & 31) == 0) wsum[tid >> 5] = a;
    __syncthreads();
    float tot = wsum[0] + wsum[1] + wsum[2] + wsum[3]
              + wsum[4] + wsum[5] + wsum[6] + wsum[7];
    float s = fmaxf(tot * (1.f / (float)DIM), 1e-5f);
    if (tid == 0) *sdst = s;

    float inv = 1.f / s;
    float w[8] = { v0.x, v0.y, v0.z, v0.w, v1.x, v1.y, v1.z, v1.w };
    __half h[8];
    #pragma unroll
    for (int i = 0; i < 8; i++) {
        float q = rintf(w[i] * inv);
        h[i] = __float2half_rn(fminf(fmaxf(q, -1.f), 1.f));   // -1/0/1 exact
    }
    *(uint4*)(dst + tid * 8) = *(uint4*)h;
}

// ---------------------------------------------------------------------------
// 4) FP16 GEMM, cp.async double-buffered: C[M,N] = (A @ T^T) * s[n]
//    BM=BN=128, BK=64, 256 threads = 8 warps (4x2), warp tile 32x64.
//    Smem stride 88 halves (16B-aligned rows, conflict-free fragments).
// ---------------------------------------------------------------------------
#define GSTR 88
#define GSTG (128 * GSTR)    // halves per stage per operand

__device__ __forceinline__ void gemm_core(
    const __half* __restrict__ A, const __half* __restrict__ B,
    const float* __restrict__ sc, float* __restrict__ C,
    __half* __restrict__ Ch, int N)
{
    extern __shared__ __half smh[];
    __half* As = smh;               // [2][128*88]
    __half* Bs = smh + 2 * GSTG;    // [2][128*88]
    const int K = DIM;
    int tid = threadIdx.x, warp = tid >> 5, lane = tid & 31;
    int g = lane >> 2, t = lane & 3;
    int wm = (warp & 3) * 32, wn = (warp >> 2) * 64;
    const __half* Ab = A + (size_t)blockIdx.y * 128 * K;
    const __half* Bb = B + (size_t)blockIdx.x * 128 * K;

    float acc[2][8][4];
    #pragma unroll
    for (int mt = 0; mt < 2; mt++)
        #pragma unroll
        for (int nt = 0; nt < 8; nt++)
            #pragma unroll
            for (int r = 0; r < 4; r++) acc[mt][nt][r] = 0.f;

    // stage loader: 128 rows x 8 chunks of 8 halves (16B) per operand
    auto load_stage = [&](int stage, int k0) {
        __half* Ad = As + stage * GSTG;
        __half* Bd = Bs + stage * GSTG;
        #pragma unroll
        for (int i = 0; i < 4; i++) {
            int l = tid + i * 256;
            int row = l >> 3, c8 = (l & 7) * 8;
            cp_async16(Ad + row * GSTR + c8, Ab + (size_t)row * K + k0 + c8);
            cp_async16(Bd + row * GSTR + c8, Bb + (size_t)row * K + k0 + c8);
        }
        CP_COMMIT();
    };

    load_stage(0, 0);
    const int nIter = K / 64;   // 32
    for (int it = 0; it < nIter; it++) {
        CP_WAIT(0);
        __syncthreads();
        if (it + 1 < nIter) load_stage((it + 1) & 1, (it + 1) * 64);

        const __half* Ac = As + (it & 1) * GSTG;
        const __half* Bc = Bs + (it & 1) * GSTG;
        #pragma unroll
        for (int kk = 0; kk < 64; kk += 16) {
            unsigned a[2][4];
            #pragma unroll
            for (int mt = 0; mt < 2; mt++) {
                const __half* ap = Ac + (wm + mt * 16 + g) * GSTR + kk + 2 * t;
                a[mt][0] = *(const unsigned*)(ap);
                a[mt][1] = *(const unsigned*)(ap + 8 * GSTR);
                a[mt][2] = *(const unsigned*)(ap + 8);
                a[mt][3] = *(const unsigned*)(ap + 8 * GSTR + 8);
            }
            #pragma unroll
            for (int nt = 0; nt < 8; nt++) {
                const __half* bp = Bc + (wn + nt * 8 + g) * GSTR + kk + 2 * t;
                unsigned b[2];
                b[0] = *(const unsigned*)(bp);
                b[1] = *(const unsigned*)(bp + 8);
                mma_f16(acc[0][nt], a[0], b);
                mma_f16(acc[1][nt], a[1], b);
            }
        }
        __syncthreads();
    }

    int brow = blockIdx.y * 128, bcol = blockIdx.x * 128;
    #pragma unroll
    for (int mt = 0; mt < 2; mt++) {
        int r0 = brow + wm + mt * 16 + g;
        #pragma unroll
        for (int nt = 0; nt < 8; nt++) {
            int c = bcol + wn + nt * 8 + 2 * t;
            float s0 = sc[c], s1 = sc[c + 1];
            float v00 = acc[mt][nt][0] * s0, v01 = acc[mt][nt][1] * s1;
            float v10 = acc[mt][nt][2] * s0, v11 = acc[mt][nt][3] * s1;
            *(float2*)(C + (size_t)r0 * N + c)       = make_float2(v00, v01);
            *(float2*)(C + (size_t)(r0 + 8) * N + c) = make_float2(v10, v11);
            if (Ch) {
                *(__half2*)(Ch + (size_t)r0 * N + c)       = __floats2half2_rn(v00, v01);
                *(__half2*)(Ch + (size_t)(r0 + 8) * N + c) = __floats2half2_rn(v10, v11);
            }
        }
    }
}

__global__ __launch_bounds__(256, 2) void gemm_qkv_kernel() {
    gemm_core(g_x_h, g_Wqkv, g_sqkv, g_QKV, g_QKVh, QKVN);
}
__global__ __launch_bounds__(256, 2) void gemm_proj_kernel(float* __restrict__ out) {
    gemm_core(g_Yh, g_Wp, g_sp, out, (__half*)0, DIM);
}
static const int GEMM_SMEM = 4 * GSTG * (int)sizeof(__half);  // 90112

// ---------------------------------------------------------------------------
// 5) Q/K post: RMSNorm (eps=2^-23) -> RoPE -> gain; f32 in, fp16 out.
// ---------------------------------------------------------------------------
__global__ __launch_bounds__(256) void qk_post_kernel(const float* __restrict__ gain) {
    int widx = blockIdx.x * 8 + (threadIdx.x >> 5);
    int lane = threadIdx.x & 31;
    if (widx >= SEQ * (NH + NKV)) return;
    int pos  = widx / (NH + NKV);
    int slot = widx - pos * (NH + NKV);

    size_t off; float gv = 1.f;
    if (slot < NH) { off = (size_t)pos * QKVN + slot * HD; gv = gain[slot]; }
    else           { off = (size_t)pos * QKVN + DIM + (slot - NH) * HD; }
    const float* p = g_QKV + off;
    __half* ph = g_QKVh + off;

    float v0 = p[lane], v1 = p[lane+32], v2 = p[lane+64], v3 = p[lane+96];
    float ss = v0*v0 + v1*v1 + v2*v2 + v3*v3;
    #pragma unroll
    for (int o = 16; o > 0; o >>= 1) ss += __shfl_xor_sync(0xffffffffu, ss, o);
    float ms = ss * (1.f / 128.f) + 1.1920928955078125e-07f;
    float r  = rsqrtf(ms);
    r = r * (1.5f - 0.5f * ms * r * r);
    v0 *= r; v1 *= r; v2 *= r; v3 *= r;

    const float* cr = g_cos + pos * 64;
    const float* sr = g_sin + pos * 64;
    float c0 = cr[lane], s0 = sr[lane], c1 = cr[lane+32], s1 = sr[lane+32];
    float o0 =  v0 * c0 + v2 * s0;
    float o2 = -v0 * s0 + v2 * c0;
    float o1 =  v1 * c1 + v3 * s1;
    float o3 = -v1 * s1 + v3 * c1;
    ph[lane]    = __float2half_rn(o0 * gv);
    ph[lane+32] = __float2half_rn(o1 * gv);
    ph[lane+64] = __float2half_rn(o2 * gv);
    ph[lane+96] = __float2half_rn(o3 * gv);
}

// ---------------------------------------------------------------------------
// 6) FP16 flash attention, cp.async pipelined, 2 blocks/SM.
//    Block = (128 q-rows, head). K double-buffered; V async over softmax.
// ---------------------------------------------------------------------------
#define FSTR 136
#define PSTR 72

__global__ __launch_bounds__(256, 2) void flash_kernel() {
    extern __shared__ __half smf[];
    __half* Qs  = smf;                    // [128][136]
    __half* Ks0 = Qs  + 128 * FSTR;       // [64][136]
    __half* Ks1 = Ks0 + 64 * FSTR;        // [64][136]
    __half* Vs  = Ks1 + 64 * FSTR;        // [64][136]
    __half* Ps  = Vs  + 64 * FSTR;        // [128][72]

    int qtile = gridDim.x - 1 - blockIdx.x;   // longest first
    int h = blockIdx.y, kvh = h >> 2;
    int qbase = qtile * 128;
    int tid = threadIdx.x, warp = tid >> 5, lane = tid & 31;
    int g = lane >> 2, t = lane & 3;
    int wbase = warp * 16;
    const float scale = 0.08838834764831845f;
    const float L2E = 1.4426950408889634f;

    // Load Q tile: 128 rows x 16 chunks(8h)
    const __half* qp = g_QKVh + (size_t)qbase * QKVN + h * HD;
    #pragma unroll
    for (int i = 0; i < 8; i++) {
        int l = tid + i * 256;
        int row = l >> 4, c8 = (l & 15) * 8;
        cp_async16(Qs + row * FSTR + c8, qp + (size_t)row * QKVN + c8);
    }
    CP_COMMIT();

    auto issueK = [&](int j, __half* Kbuf) {
        const __half* kp = g_QKVh + (size_t)(j * 64) * QKVN + DIM + kvh * HD;
        #pragma unroll
        for (int i = 0; i < 4; i++) {
            int l = tid + i * 256;
            int row = l >> 4, c8 = (l & 15) * 8;
            cp_async16(Kbuf + row * FSTR + c8, kp + (size_t)row * QKVN + c8);
        }
        CP_COMMIT();
    };
    auto issueV = [&](int j) {
        const __half* vp = g_QKVh + (size_t)(j * 64) * QKVN + DIM + KVDIM + kvh * HD;
        #pragma unroll
        for (int i = 0; i < 4; i++) {
            int l = tid + i * 256;
            int row = l >> 4, c8 = (l & 15) * 8;
            cp_async16(Vs + row * FSTR + c8, vp + (size_t)row * QKVN + c8);
        }
        CP_COMMIT();
    };

    float oacc[16][4];
    #pragma unroll
    for (int nt = 0; nt < 16; nt++)
        #pragma unroll
        for (int r = 0; r < 4; r++) oacc[nt][r] = 0.f;
    float m0 = -1e30f, m1 = -1e30f, l0 = 0.f, l1 = 0.f;

    int row0 = qbase + wbase + g, row1 = row0 + 8;
    int jmax = 2 * qtile + 1;

    issueK(0, Ks0);   // groups in flight: [Q, K0]

    for (int j = 0; j <= jmax; j++) {
        int kvbase = j * 64;
        __syncthreads();               // Vs free (prev PV done)
        issueV(j);
        int jn = (j + 1 <= jmax) ? j + 1 : jmax;
        issueK(jn, (j & 1) ? Ks0 : Ks1);
        CP_WAIT(2);                    // Q + K(j) ready; V(j), K(j+1) may pend
        __syncthreads();
        const __half* Kc = (j & 1) ? Ks1 : Ks0;

        // --- S = Q @ K^T ---
        float sacc[8][4];
        #pragma unroll
        for (int nt = 0; nt < 8; nt++)
            #pragma unroll
            for (int r = 0; r < 4; r++) sacc[nt][r] = 0.f;
        #pragma unroll
        for (int kk = 0; kk < 128; kk += 16) {
            unsigned a[4];
            const __half* ap = Qs + (wbase + g) * FSTR + kk + 2 * t;
            a[0] = *(const unsigned*)(ap);
            a[1] = *(const unsigned*)(ap + 8 * FSTR);
            a[2] = *(const unsigned*)(ap + 8);
            a[3] = *(const unsigned*)(ap + 8 * FSTR + 8);
            #pragma unroll
            for (int nt = 0; nt < 8; nt++) {
                const __half* bp = Kc + (nt * 8 + g) * FSTR + kk + 2 * t;
                unsigned b[2];
                b[0] = *(const unsigned*)(bp);
                b[1] = *(const unsigned*)(bp + 8);
                mma_f16(sacc[nt], a, b);
            }
        }

        // --- scale + causal mask + online softmax ---
        float mn0 = m0, mn1 = m1;
        #pragma unroll
        for (int nt = 0; nt < 8; nt++) {
            int c0 = kvbase + nt * 8 + 2 * t, c1 = c0 + 1;
            float v0 = (c0 <= row0) ? sacc[nt][0] * scale : -1e30f;
            float v1 = (c1 <= row0) ? sacc[nt][1] * scale : -1e30f;
            float v2 = (c0 <= row1) ? sacc[nt][2] * scale : -1e30f;
            float v3 = (c1 <= row1) ? sacc[nt][3] * scale : -1e30f;
            sacc[nt][0] = v0; sacc[nt][1] = v1; sacc[nt][2] = v2; sacc[nt][3] = v3;
            mn0 = fmaxf(mn0, fmaxf(v0, v1));
            mn1 = fmaxf(mn1, fmaxf(v2, v3));
        }
        mn0 = fmaxf(mn0, __shfl_xor_sync(0xffffffffu, mn0, 1));
        mn0 = fmaxf(mn0, __shfl_xor_sync(0xffffffffu, mn0, 2));
        mn1 = fmaxf(mn1, __shfl_xor_sync(0xffffffffu, mn1, 1));
        mn1 = fmaxf(mn1, __shfl_xor_sync(0xffffffffu, mn1, 2));
        float a0 = exp2f((m0 - mn0) * L2E);
        float a1 = exp2f((m1 - mn1) * L2E);
        m0 = mn0; m1 = mn1;
        float s0 = 0.f, s1 = 0.f;
        __half* pr0 = Ps + (wbase + g) * PSTR + 2 * t;
        __half* pr1 = pr0 + 8 * PSTR;
        #pragma unroll
        for (int nt = 0; nt < 8; nt++) {
            float p0 = exp2f((sacc[nt][0] - m0) * L2E);
            float p1 = exp2f((sacc[nt][1] - m0) * L2E);
            float p2 = exp2f((sacc[nt][2] - m1) * L2E);
            float p3 = exp2f((sacc[nt][3] - m1) * L2E);
            s0 += p0 + p1; s1 += p2 + p3;
            *(__half2*)(pr0 + nt * 8) = __floats2half2_rn(p0, p1);
            *(__half2*)(pr1 + nt * 8) = __floats2half2_rn(p2, p3);
        }
        s0 += __shfl_xor_sync(0xffffffffu, s0, 1);
        s0 += __shfl_xor_sync(0xffffffffu, s0, 2);
        s1 += __shfl_xor_sync(0xffffffffu, s1, 1);
        s1 += __shfl_xor_sync(0xffffffffu, s1, 2);
        l0 = l0 * a0 + s0;
        l1 = l1 * a1 + s1;
        #pragma unroll
        for (int nt = 0; nt < 16; nt++) {
            oacc[nt][0] *= a0; oacc[nt][1] *= a0;
            oacc[nt][2] *= a1; oacc[nt][3] *= a1;
        }

        CP_WAIT(1);                    // V(j) ready (K(j+1) may pend)
        __syncthreads();

        // --- O += P @ V ---
        #pragma unroll
        for (int kk = 0; kk < 64; kk += 16) {
            unsigned a[4];
            const __half* ap = Ps + (wbase + g) * PSTR + kk + 2 * t;
            a[0] = *(const unsigned*)(ap);
            a[1] = *(const unsigned*)(ap + 8 * PSTR);
            a[2] = *(const unsigned*)(ap + 8);
            a[3] = *(const unsigned*)(ap + 8 * PSTR + 8);
            #pragma unroll
            for (int nt = 0; nt < 16; nt++) {
                int col = nt * 8 + g;
                const __half* vb = Vs + (kk + 2 * t) * FSTR + col;
                unsigned b[2];
                b[0] = pack2(vb[0],        vb[FSTR]);
                b[1] = pack2(vb[8 * FSTR], vb[9 * FSTR]);
                mma_f16(oacc[nt], a, b);
            }
        }
    }

    // --- epilogue: O /= l, write Yh (fp16) ---
    float i0 = 1.f / l0, i1 = 1.f / l1;
    __half* y0 = g_Yh + (size_t)(qbase + wbase + g) * DIM + h * HD + 2 * t;
    __half* y1 = y0 + 8 * DIM;
    #pragma unroll
    for (int nt = 0; nt < 16; nt++) {
        *(__half2*)(y0 + nt * 8) = __floats2half2_rn(oacc[nt][0] * i0, oacc[nt][1] * i0);
        *(__half2*)(y1 + nt * 8) = __floats2half2_rn(oacc[nt][2] * i1, oacc[nt][3] * i1);
    }
}

static const int FLASH_SMEM =
    (128 * FSTR + 2 * 64 * FSTR + 64 * FSTR + 128 * PSTR) * (int)sizeof(__half);  // 105472

// ---------------------------------------------------------------------------
// Launch
// ---------------------------------------------------------------------------
extern "C" void kernel_launch(void* const* d_in, const int* in_sizes, int n_in,
                              void* d_out, int out_size)
{
    const float* x    = (const float*)d_in[0];
    const float* wq   = (const float*)d_in[1];
    const float* wk   = (const float*)d_in[2];
    const float* wv   = (const float*)d_in[3];
    const float* wp   = (const float*)d_in[4];
    const float* gain = (const float*)d_in[5];
    float* out = (float*)d_out;

    cudaFuncSetAttribute(flash_kernel,
                         cudaFuncAttributeMaxDynamicSharedMemorySize, FLASH_SMEM);
    cudaFuncSetAttribute(gemm_qkv_kernel,
                         cudaFuncAttributeMaxDynamicSharedMemorySize, GEMM_SMEM);
    cudaFuncSetAttribute(gemm_proj_kernel,
                         cudaFuncAttributeMaxDynamicSharedMemorySize, GEMM_SMEM);

    invf_kernel<<<1, 64>>>();
    rope_table_kernel<<<(SEQ * (HD/2) + 255) / 256, 256>>>();
    xh_kernel<<<SEQ * DIM / 1024, 256>>>(x);
    quantize_kernel<<<NROWS_W, 256>>>(wq, wk, wv, wp);
    gemm_qkv_kernel<<<dim3(QKVN / 128, SEQ / 128), 256, GEMM_SMEM>>>();
    qk_post_kernel<<<(SEQ * (NH + NKV) + 7) / 8, 256>>>(gain);
    flash_kernel<<<dim3(SEQ / 128, NH), 256, FLASH_SMEM>>>();
    gemm_proj_kernel<<<dim3(DIM / 128, SEQ / 128), 256, GEMM_SMEM>>>(out);
}